// round 15
// baseline (speedup 1.0000x reference)
#include <cuda_runtime.h>
#include <math.h>

#define DIMN 3
#define NPTS 30
#define KK   181
#define PP   24360          // 30*29*28
#define DE   190            // 9 + 181
#define RESTN 27

// K3 half-segment counting sort (atomic-halved)
#define HALF_N   12180
#define K3A_THREADS 1024
#define K3A_BINS 8192
// smem: B[HALF_N]f + hist[K3A_BINS]u32 + rank[HALF_N]u16 + temps  ~= 104 KB -> 2 CTAs/SM
#define K3A_SMEM (HALF_N * 4 + K3A_BINS * 4 + HALF_N * 2 + 512)

// ------------------------- device scratch (static, allowed) -------------------------
// +64 floats padding: K2's cp.async prefetch of the ragged last p-tile may read
// up to 63 elements past PP in the last row; keep that inside the allocation.
__device__ __align__(16) float g_vecT[(size_t)DE * PP + 64]; // (190, P) TRANSPOSED vec
__device__ float g_wsT[190 * 192];                      // Ws_out transposed, padded
__device__ float g_wdT[RESTN * KK];                     // WdIn transposed (27, 181)
__device__ __align__(16) float g_sm2T[(size_t)KK * PP]; // (K, P) column-major sm2
__device__ __align__(16) float g_srt[(size_t)KK * PP];  // sorted half-runs

// ------------------------- K0: transpose Ws_out -------------------------
__global__ void k0_transpose(const float* __restrict__ WsOut) {
    int j = blockIdx.x;          // 0..189
    int t = threadIdx.x;         // 0..191
    g_wsT[j * 192 + t] = (t < KK) ? WsOut[t * DE + j] : 0.0f;
}

// ------------------------- K0b: transpose Wd_in -------------------------
__global__ void k0b_transpose(const float* __restrict__ WdIn) {
    int m = blockIdx.x;          // 0..26
    int t = threadIdx.x;         // 0..191
    if (t < KK) g_wdT[m * KK + t] = WdIn[t * RESTN + m];
}

// ------------------------- K1: per-permutation vec rows (transposed store) ------------
__global__ void k1_vec(const float* __restrict__ matrix,
                       const float* __restrict__ WsIn) {
    __shared__ float mS[DIMN * NPTS];      // 90
    __shared__ float projS[DIMN][RESTN];   // 3x27
    __shared__ float gramS[9];

    const int p = blockIdx.x;
    const int t = threadIdx.x;             // 0..191

    // decode lexicographic permutation p -> (a,b,c)
    int a  = p / 812;                // 812 = 29*28
    int r  = p - a * 812;
    int bi = r / 28;
    int ci = r - bi * 28;
    int b  = bi + (bi >= a);
    int e0 = min(a, b), e1 = max(a, b);
    int c  = ci + (ci >= e0);
    c += (c >= e1);

    // sorted excluded triple for rest[]
    int s0 = min(a, min(b, c));
    int s2 = max(a, max(b, c));
    int s1 = a + b + c - s0 - s2;

    if (t < DIMN * NPTS) mS[t] = matrix[t];
    __syncthreads();

    if (t < DIMN * RESTN) {
        int i = t / RESTN, m = t - i * RESTN;
        int rm = m + (m >= s0); rm += (rm >= s1); rm += (rm >= s2);
        int ci_ = (i == 0) ? a : ((i == 1) ? b : c);
        projS[i][m] = mS[ci_] * mS[rm]
                    + mS[NPTS + ci_] * mS[NPTS + rm]
                    + mS[2 * NPTS + ci_] * mS[2 * NPTS + rm];
    } else if (t < DIMN * RESTN + 9) {
        int q = t - DIMN * RESTN;
        int i = q / 3, j = q - 3 * i;
        int ci_ = (i == 0) ? a : ((i == 1) ? b : c);
        int cj_ = (j == 0) ? a : ((j == 1) ? b : c);
        gramS[q] = mS[ci_] * mS[cj_]
                 + mS[NPTS + ci_] * mS[NPTS + cj_]
                 + mS[2 * NPTS + ci_] * mS[2 * NPTS + cj_];
    }
    __syncthreads();

    if (t < 9) g_vecT[(size_t)t * PP + p] = gramS[t];

    if (t < KK) {
        const int k = t;
        const float w0 = WsIn[k * 3 + 0];
        const float w1 = WsIn[k * 3 + 1];
        const float w2 = WsIn[k * 3 + 2];

        float v[32];
#pragma unroll
        for (int m = 0; m < RESTN; ++m)
            v[m] = fmaf(projS[2][m], w2, fmaf(projS[1][m], w1, projS[0][m] * w0));
        const float INF = __int_as_float(0x7f800000);
#pragma unroll
        for (int m = RESTN; m < 32; ++m) v[m] = INF;

        // fully-unrolled 32-element bitonic sort (ascending), registers only
#pragma unroll
        for (int size = 2; size <= 32; size <<= 1) {
#pragma unroll
            for (int stride = size >> 1; stride > 0; stride >>= 1) {
#pragma unroll
                for (int i = 0; i < 32; ++i) {
                    int j = i ^ stride;
                    if (j > i) {
                        bool up = ((i & size) == 0);
                        float x = v[i], y = v[j];
                        float lo = fminf(x, y), hi = fmaxf(x, y);
                        v[i] = up ? lo : hi;
                        v[j] = up ? hi : lo;
                    }
                }
            }
        }

        float e = 0.0f;
#pragma unroll
        for (int m = 0; m < RESTN; ++m)
            e = fmaf(g_wdT[m * KK + k], v[m], e);   // coalesced, L1-resident
        g_vecT[(size_t)(9 + k) * PP + p] = e;
    }
}

// ------------------------- K2: sm2T[k][p] = vec[p] . Ws_out[k] -------------------------
// packed f32x2 FMA (pair along k) + cp.async double-buffered tile pipeline
#define TP 64
#define JC 19
#define NTILE (DE / JC)      // 10

__device__ __forceinline__ void ffma2(unsigned long long& d,
                                      unsigned long long a,
                                      unsigned long long b) {
    asm("fma.rn.f32x2 %0, %1, %2, %0;" : "+l"(d) : "l"(a), "l"(b));
}
__device__ __forceinline__ unsigned long long dup_f32(float x) {
    unsigned long long r;
    unsigned int u = __float_as_uint(x);
    asm("mov.b64 %0, {%1, %1};" : "=l"(r) : "r"(u));
    return r;
}
__device__ __forceinline__ void cp16(void* smem, const void* gmem) {
    unsigned int saddr = (unsigned int)__cvta_generic_to_shared(smem);
    asm volatile("cp.async.ca.shared.global [%0], [%1], 16;"
                 :: "r"(saddr), "l"(gmem));
}

__global__ void __launch_bounds__(256)
k2_gemm() {
    __shared__ __align__(16) float vS[2][JC][TP];    // 2 x 4.9 KB
    __shared__ __align__(16) float wS[2][JC][192];   // 2 x 14.6 KB

    const int p0 = blockIdx.x * TP;
    const int t  = threadIdx.x;         // 256
    const int pt = t & 15;              // 16 p-threads (4 p each)
    const int kt = t >> 4;              // 16 k-threads (12 k each = 6 pairs)

    unsigned long long acc2[4][6];      // [p][k-pair]
#pragma unroll
    for (int r0 = 0; r0 < 4; ++r0)
#pragma unroll
        for (int cc = 0; cc < 6; ++cc) acc2[r0][cc] = 0ull;

    // ---- async tile loader: tile tt (j0 = tt*JC) into buffer b ----
    auto load_tile = [&](int tt, int b) {
        const int j0 = tt * JC;
        for (int idx = t; idx < JC * TP / 4; idx += 256) {
            int row = idx >> 4;
            int col = idx & 15;
            cp16(&vS[b][row][col * 4],
                 &g_vecT[(size_t)(j0 + row) * PP + p0 + col * 4]);
        }
        for (int idx = t; idx < JC * 192 / 4; idx += 256) {
            int row = idx / 48;
            int col = idx - row * 48;
            cp16(&wS[b][row][col * 4],
                 &g_wsT[(j0 + row) * 192 + col * 4]);
        }
    };

    load_tile(0, 0);
    asm volatile("cp.async.commit_group;");

    for (int tt = 0; tt < NTILE; ++tt) {
        if (tt + 1 < NTILE) load_tile(tt + 1, (tt + 1) & 1);
        asm volatile("cp.async.commit_group;");
        asm volatile("cp.async.wait_group 1;");
        __syncthreads();

        const int b = tt & 1;
#pragma unroll
        for (int jj = 0; jj < JC; ++jj) {
            float4 rv = *reinterpret_cast<const float4*>(&vS[b][jj][pt * 4]);
            unsigned long long rr2[4] = {dup_f32(rv.x), dup_f32(rv.y),
                                         dup_f32(rv.z), dup_f32(rv.w)};
            const unsigned long long* wrow =
                reinterpret_cast<const unsigned long long*>(&wS[b][jj][0]);
            unsigned long long w2[6];
#pragma unroll
            for (int cc = 0; cc < 6; ++cc) w2[cc] = wrow[kt * 6 + cc];
#pragma unroll
            for (int cc = 0; cc < 6; ++cc)
#pragma unroll
                for (int r0 = 0; r0 < 4; ++r0)
                    ffma2(acc2[r0][cc], rr2[r0], w2[cc]);
        }
        __syncthreads();
    }

    const bool full = (p0 + TP <= PP);
#pragma unroll
    for (int cc = 0; cc < 6; ++cc) {
#pragma unroll
        for (int half = 0; half < 2; ++half) {
            int k = kt * 12 + 2 * cc + half;
            if (k >= KK) continue;
            float a0, a1, a2, a3;
            if (half == 0) {
                a0 = __uint_as_float((unsigned int)(acc2[0][cc] & 0xffffffffull));
                a1 = __uint_as_float((unsigned int)(acc2[1][cc] & 0xffffffffull));
                a2 = __uint_as_float((unsigned int)(acc2[2][cc] & 0xffffffffull));
                a3 = __uint_as_float((unsigned int)(acc2[3][cc] & 0xffffffffull));
            } else {
                a0 = __uint_as_float((unsigned int)(acc2[0][cc] >> 32));
                a1 = __uint_as_float((unsigned int)(acc2[1][cc] >> 32));
                a2 = __uint_as_float((unsigned int)(acc2[2][cc] >> 32));
                a3 = __uint_as_float((unsigned int)(acc2[3][cc] >> 32));
            }
            size_t base = (size_t)k * PP + p0 + pt * 4;
            if (full) {
                *reinterpret_cast<float4*>(&g_sm2T[base]) = make_float4(a0, a1, a2, a3);
            } else {
                float av[4] = {a0, a1, a2, a3};
#pragma unroll
                for (int r0 = 0; r0 < 4; ++r0) {
                    int p = p0 + pt * 4 + r0;
                    if (p < PP) g_sm2T[(size_t)k * PP + p] = av[r0];
                }
            }
        }
    }
}

// ------------------------- K3a: half-segment counting sort, atomic-halved --------------
// Pass 1: minmax. Pass 2: hist atomics, SAVING each element's intra-bin rank (u16).
// Pass 3 scatter is atomic-free: pos = start[bin] + savedRank. hist[] keeps the
// exclusive starts (never mutated after scan), giving exact run bounds for cleanup.
__global__ void __launch_bounds__(K3A_THREADS, 2)
k3a_half_sort() {
    extern __shared__ __align__(16) char smem_raw[];
    float* B = (float*)smem_raw;                                  // HALF_N
    unsigned int* hist = (unsigned int*)(smem_raw + HALF_N * 4);  // K3A_BINS
    unsigned short* rankA =
        (unsigned short*)(smem_raw + HALF_N * 4 + K3A_BINS * 4);  // HALF_N
    float* wmin = (float*)(rankA + HALF_N);                       // 32
    float* wmax = wmin + 32;                                      // 32
    unsigned int* wsum = (unsigned int*)(wmax + 32);              // 32

    const int k = blockIdx.x >> 1;
    const int h = blockIdx.x & 1;
    const int t = threadIdx.x;
    const int lane = t & 31, wid = t >> 5;
    const float* __restrict__ src = g_sm2T + (size_t)k * PP + h * HALF_N;

    // ---- pass 1: min/max + zero hist ----
    float mn = __int_as_float(0x7f800000), mx = -mn;
    for (int i = t; i < HALF_N; i += K3A_THREADS) {
        float x = src[i];
        mn = fminf(mn, x);
        mx = fmaxf(mx, x);
    }
#pragma unroll
    for (int o = 16; o > 0; o >>= 1) {
        mn = fminf(mn, __shfl_xor_sync(0xffffffffu, mn, o));
        mx = fmaxf(mx, __shfl_xor_sync(0xffffffffu, mx, o));
    }
    if (lane == 0) { wmin[wid] = mn; wmax[wid] = mx; }
    for (int b = t; b < K3A_BINS; b += K3A_THREADS) hist[b] = 0u;
    __syncthreads();
    if (t < 32) {
        float a = wmin[t], b = wmax[t];
#pragma unroll
        for (int o = 16; o > 0; o >>= 1) {
            a = fminf(a, __shfl_xor_sync(0xffffffffu, a, o));
            b = fmaxf(b, __shfl_xor_sync(0xffffffffu, b, o));
        }
        if (t == 0) { wmin[0] = a; wmax[0] = b; }
    }
    __syncthreads();
    mn = wmin[0]; mx = wmax[0];
    const float width = mx - mn;
    const float scale = (width > 0.0f) ? (float)K3A_BINS / width : 0.0f;
    __syncthreads();

    // ---- pass 2: histogram + save intra-bin rank ----
    for (int i = t; i < HALF_N; i += K3A_THREADS) {
        int bin = min(K3A_BINS - 1, (int)((src[i] - mn) * scale));
        unsigned int old = atomicAdd(&hist[bin], 1u);
        rankA[i] = (unsigned short)old;
    }
    __syncthreads();

    // ---- exclusive scan of hist (8 bins/thread); hist becomes starts ----
    const int bb = t * (K3A_BINS / K3A_THREADS);
    unsigned int s = 0;
#pragma unroll
    for (int i = 0; i < K3A_BINS / K3A_THREADS; ++i) s += hist[bb + i];
    unsigned int sc = s;
#pragma unroll
    for (int o = 1; o < 32; o <<= 1) {
        unsigned int u = __shfl_up_sync(0xffffffffu, sc, o);
        if (lane >= o) sc += u;
    }
    if (lane == 31) wsum[wid] = sc;
    __syncthreads();
    if (t < 32) {
        unsigned int v = wsum[t], vs = v;
#pragma unroll
        for (int o = 1; o < 32; o <<= 1) {
            unsigned int u = __shfl_up_sync(0xffffffffu, vs, o);
            if (t >= o) vs += u;
        }
        wsum[t] = vs - v;
    }
    __syncthreads();
    unsigned int run = wsum[wid] + (sc - s);
#pragma unroll
    for (int i = 0; i < K3A_BINS / K3A_THREADS; ++i) {
        unsigned int c = hist[bb + i];
        hist[bb + i] = run;          // exclusive start; NOT mutated afterwards
        run += c;
    }
    __syncthreads();

    // ---- pass 3: atomic-free scatter ----
    for (int i = t; i < HALF_N; i += K3A_THREADS) {
        float x = src[i];
        int bin = min(K3A_BINS - 1, (int)((x - mn) * scale));
        B[hist[bin] + rankA[i]] = x;
    }
    __syncthreads();

    // ---- per-bin insertion sort (exact; run b = [hist[b], hist[b+1])) ----
    if (scale != 0.0f) {
        for (int b = t; b < K3A_BINS; b += K3A_THREADS) {
            int st = (int)hist[b];
            int e = (b == K3A_BINS - 1) ? HALF_N : (int)hist[b + 1];
            for (int a2 = st + 1; a2 < e; ++a2) {
                float x = B[a2];
                int j = a2 - 1;
                while (j >= st && B[j] > x) { B[j + 1] = B[j]; --j; }
                B[j + 1] = x;
            }
        }
    }
    __syncthreads();

    // ---- write sorted half (coalesced) ----
    float* dst = g_srt + (size_t)blockIdx.x * HALF_N;
    for (int i = t; i < HALF_N; i += K3A_THREADS) dst[i] = B[i];
}

// ------------------------- K3b: merge-path merge + weighted dot ------------------------
__global__ void __launch_bounds__(1024)
k3b_mergedot(const float* __restrict__ WdOut, float* __restrict__ out) {
    __shared__ float red[32];
    const int k = blockIdx.x;
    const int t = threadIdx.x;

    const float* A = g_srt + (size_t)(k * 2) * HALF_N;
    const float* B = A + HALF_N;
    const int nA = HALF_N, nB = HALF_N;

    const int d0 = t * 24;             // 1015*24 = 24360 exactly
    float acc = 0.0f;
    if (d0 < PP) {
        // merge-path partition; tie rule: A wins
        int lo = max(0, d0 - nB), hi = min(d0, nA);
        while (lo < hi) {
            int mid = (lo + hi) >> 1;
            if (A[mid] <= B[d0 - mid - 1]) lo = mid + 1;
            else hi = mid;
        }
        int i = lo, j = d0 - lo;

        const float* wd = WdOut + (size_t)k * PP + d0;
#pragma unroll 4
        for (int q = 0; q < 24; ++q) {
            bool takeA = (j >= nB) || (i < nA && A[i] <= B[j]);
            float val = takeA ? A[i] : B[j];
            i += takeA;
            j += !takeA;
            acc = fmaf(wd[q], val, acc);
        }
    }

#pragma unroll
    for (int o = 16; o > 0; o >>= 1)
        acc += __shfl_down_sync(0xffffffffu, acc, o);
    if ((t & 31) == 0) red[t >> 5] = acc;
    __syncthreads();
    if (t < 32) {
        float x = red[t];
#pragma unroll
        for (int o = 16; o > 0; o >>= 1)
            x += __shfl_down_sync(0xffffffffu, x, o);
        if (t == 0) out[k] = x;
    }
}

// ------------------------- launch -------------------------
extern "C" void kernel_launch(void* const* d_in, const int* in_sizes, int n_in,
                              void* d_out, int out_size) {
    const float* matrix = (const float*)d_in[0];
    const float* WsIn   = (const float*)d_in[1];
    const float* WdIn   = (const float*)d_in[2];
    const float* WsOut  = (const float*)d_in[3];
    const float* WdOut  = (const float*)d_in[4];
    float* out = (float*)d_out;

    cudaFuncSetAttribute(k3a_half_sort, cudaFuncAttributeMaxDynamicSharedMemorySize,
                         K3A_SMEM);

    k0_transpose<<<DE, 192>>>(WsOut);
    k0b_transpose<<<RESTN, 192>>>(WdIn);
    k1_vec<<<PP, 192>>>(matrix, WsIn);
    k2_gemm<<<(PP + TP - 1) / TP, 256>>>();
    k3a_half_sort<<<KK * 2, K3A_THREADS, K3A_SMEM>>>();
    k3b_mergedot<<<KK, 1024>>>(WdOut, out);
}

// round 16
// speedup vs baseline: 1.0373x; 1.0373x over previous
#include <cuda_runtime.h>
#include <math.h>

#define DIMN 3
#define NPTS 30
#define KK   181
#define PP   24360          // 30*29*28
#define DE   190            // 9 + 181
#define RESTN 27
#define NBINS 16384

// dynamic smem for k3: B[PP]f + hist[NBINS]u32 + rank[PP]u16 + temps  ~= 212 KB
#define K3_SMEM (PP * 4 + NBINS * 4 + PP * 2 + 512)

// ------------------------- device scratch (static, allowed) -------------------------
// +64 floats padding: K2's cp.async prefetch of the ragged last p-tile may read
// up to 63 elements past PP in the last row; keep that inside the allocation.
__device__ __align__(16) float g_vecT[(size_t)DE * PP + 64]; // (190, P) TRANSPOSED vec
__device__ float g_wsT[190 * 192];                      // Ws_out transposed, padded
__device__ float g_wdT[RESTN * KK];                     // WdIn transposed (27, 181)
__device__ __align__(16) float g_sm2T[(size_t)KK * PP]; // (K, P) column-major sm2

// ------------------------- K0: transpose Ws_out -------------------------
__global__ void k0_transpose(const float* __restrict__ WsOut) {
    int j = blockIdx.x;          // 0..189
    int t = threadIdx.x;         // 0..191
    g_wsT[j * 192 + t] = (t < KK) ? WsOut[t * DE + j] : 0.0f;
}

// ------------------------- K0b: transpose Wd_in -------------------------
__global__ void k0b_transpose(const float* __restrict__ WdIn) {
    int m = blockIdx.x;          // 0..26
    int t = threadIdx.x;         // 0..191
    if (t < KK) g_wdT[m * KK + t] = WdIn[t * RESTN + m];
}

// ------------------------- K1: per-permutation vec rows (transposed store) ------------
__global__ void k1_vec(const float* __restrict__ matrix,
                       const float* __restrict__ WsIn) {
    __shared__ float mS[DIMN * NPTS];      // 90
    __shared__ float projS[DIMN][RESTN];   // 3x27
    __shared__ float gramS[9];

    const int p = blockIdx.x;
    const int t = threadIdx.x;             // 0..191

    // decode lexicographic permutation p -> (a,b,c)
    int a  = p / 812;                // 812 = 29*28
    int r  = p - a * 812;
    int bi = r / 28;
    int ci = r - bi * 28;
    int b  = bi + (bi >= a);
    int e0 = min(a, b), e1 = max(a, b);
    int c  = ci + (ci >= e0);
    c += (c >= e1);

    // sorted excluded triple for rest[]
    int s0 = min(a, min(b, c));
    int s2 = max(a, max(b, c));
    int s1 = a + b + c - s0 - s2;

    if (t < DIMN * NPTS) mS[t] = matrix[t];
    __syncthreads();

    if (t < DIMN * RESTN) {
        int i = t / RESTN, m = t - i * RESTN;
        int rm = m + (m >= s0); rm += (rm >= s1); rm += (rm >= s2);
        int ci_ = (i == 0) ? a : ((i == 1) ? b : c);
        projS[i][m] = mS[ci_] * mS[rm]
                    + mS[NPTS + ci_] * mS[NPTS + rm]
                    + mS[2 * NPTS + ci_] * mS[2 * NPTS + rm];
    } else if (t < DIMN * RESTN + 9) {
        int q = t - DIMN * RESTN;
        int i = q / 3, j = q - 3 * i;
        int ci_ = (i == 0) ? a : ((i == 1) ? b : c);
        int cj_ = (j == 0) ? a : ((j == 1) ? b : c);
        gramS[q] = mS[ci_] * mS[cj_]
                 + mS[NPTS + ci_] * mS[NPTS + cj_]
                 + mS[2 * NPTS + ci_] * mS[2 * NPTS + cj_];
    }
    __syncthreads();

    if (t < 9) g_vecT[(size_t)t * PP + p] = gramS[t];

    if (t < KK) {
        const int k = t;
        const float w0 = WsIn[k * 3 + 0];
        const float w1 = WsIn[k * 3 + 1];
        const float w2 = WsIn[k * 3 + 2];

        float v[32];
#pragma unroll
        for (int m = 0; m < RESTN; ++m)
            v[m] = fmaf(projS[2][m], w2, fmaf(projS[1][m], w1, projS[0][m] * w0));
        const float INF = __int_as_float(0x7f800000);
#pragma unroll
        for (int m = RESTN; m < 32; ++m) v[m] = INF;

        // fully-unrolled 32-element bitonic sort (ascending), registers only
#pragma unroll
        for (int size = 2; size <= 32; size <<= 1) {
#pragma unroll
            for (int stride = size >> 1; stride > 0; stride >>= 1) {
#pragma unroll
                for (int i = 0; i < 32; ++i) {
                    int j = i ^ stride;
                    if (j > i) {
                        bool up = ((i & size) == 0);
                        float x = v[i], y = v[j];
                        float lo = fminf(x, y), hi = fmaxf(x, y);
                        v[i] = up ? lo : hi;
                        v[j] = up ? hi : lo;
                    }
                }
            }
        }

        float e = 0.0f;
#pragma unroll
        for (int m = 0; m < RESTN; ++m)
            e = fmaf(g_wdT[m * KK + k], v[m], e);   // coalesced, L1-resident
        g_vecT[(size_t)(9 + k) * PP + p] = e;
    }
}

// ------------------------- K2: sm2T[k][p] = vec[p] . Ws_out[k] -------------------------
// packed f32x2 FMA (pair along k) + cp.async double-buffered tile pipeline
#define TP 64
#define JC 19
#define NTILE (DE / JC)      // 10

__device__ __forceinline__ void ffma2(unsigned long long& d,
                                      unsigned long long a,
                                      unsigned long long b) {
    asm("fma.rn.f32x2 %0, %1, %2, %0;" : "+l"(d) : "l"(a), "l"(b));
}
__device__ __forceinline__ unsigned long long dup_f32(float x) {
    unsigned long long r;
    unsigned int u = __float_as_uint(x);
    asm("mov.b64 %0, {%1, %1};" : "=l"(r) : "r"(u));
    return r;
}
__device__ __forceinline__ void cp16(void* smem, const void* gmem) {
    unsigned int saddr = (unsigned int)__cvta_generic_to_shared(smem);
    asm volatile("cp.async.ca.shared.global [%0], [%1], 16;"
                 :: "r"(saddr), "l"(gmem));
}

__global__ void __launch_bounds__(256)
k2_gemm() {
    __shared__ __align__(16) float vS[2][JC][TP];    // 2 x 4.9 KB
    __shared__ __align__(16) float wS[2][JC][192];   // 2 x 14.6 KB

    const int p0 = blockIdx.x * TP;
    const int t  = threadIdx.x;         // 256
    const int pt = t & 15;              // 16 p-threads (4 p each)
    const int kt = t >> 4;              // 16 k-threads (12 k each = 6 pairs)

    unsigned long long acc2[4][6];      // [p][k-pair]
#pragma unroll
    for (int r0 = 0; r0 < 4; ++r0)
#pragma unroll
        for (int cc = 0; cc < 6; ++cc) acc2[r0][cc] = 0ull;

    // ---- async tile loader: tile tt (j0 = tt*JC) into buffer b ----
    auto load_tile = [&](int tt, int b) {
        const int j0 = tt * JC;
        for (int idx = t; idx < JC * TP / 4; idx += 256) {
            int row = idx >> 4;
            int col = idx & 15;
            cp16(&vS[b][row][col * 4],
                 &g_vecT[(size_t)(j0 + row) * PP + p0 + col * 4]);
        }
        for (int idx = t; idx < JC * 192 / 4; idx += 256) {
            int row = idx / 48;
            int col = idx - row * 48;
            cp16(&wS[b][row][col * 4],
                 &g_wsT[(j0 + row) * 192 + col * 4]);
        }
    };

    load_tile(0, 0);
    asm volatile("cp.async.commit_group;");

    for (int tt = 0; tt < NTILE; ++tt) {
        if (tt + 1 < NTILE) load_tile(tt + 1, (tt + 1) & 1);
        asm volatile("cp.async.commit_group;");
        asm volatile("cp.async.wait_group 1;");
        __syncthreads();

        const int b = tt & 1;
#pragma unroll
        for (int jj = 0; jj < JC; ++jj) {
            float4 rv = *reinterpret_cast<const float4*>(&vS[b][jj][pt * 4]);
            unsigned long long rr2[4] = {dup_f32(rv.x), dup_f32(rv.y),
                                         dup_f32(rv.z), dup_f32(rv.w)};
            const unsigned long long* wrow =
                reinterpret_cast<const unsigned long long*>(&wS[b][jj][0]);
            unsigned long long w2[6];
#pragma unroll
            for (int cc = 0; cc < 6; ++cc) w2[cc] = wrow[kt * 6 + cc];
#pragma unroll
            for (int cc = 0; cc < 6; ++cc)
#pragma unroll
                for (int r0 = 0; r0 < 4; ++r0)
                    ffma2(acc2[r0][cc], rr2[r0], w2[cc]);
        }
        __syncthreads();
    }

    const bool full = (p0 + TP <= PP);
#pragma unroll
    for (int cc = 0; cc < 6; ++cc) {
#pragma unroll
        for (int half = 0; half < 2; ++half) {
            int k = kt * 12 + 2 * cc + half;
            if (k >= KK) continue;
            float a0, a1, a2, a3;
            if (half == 0) {
                a0 = __uint_as_float((unsigned int)(acc2[0][cc] & 0xffffffffull));
                a1 = __uint_as_float((unsigned int)(acc2[1][cc] & 0xffffffffull));
                a2 = __uint_as_float((unsigned int)(acc2[2][cc] & 0xffffffffull));
                a3 = __uint_as_float((unsigned int)(acc2[3][cc] & 0xffffffffull));
            } else {
                a0 = __uint_as_float((unsigned int)(acc2[0][cc] >> 32));
                a1 = __uint_as_float((unsigned int)(acc2[1][cc] >> 32));
                a2 = __uint_as_float((unsigned int)(acc2[2][cc] >> 32));
                a3 = __uint_as_float((unsigned int)(acc2[3][cc] >> 32));
            }
            size_t base = (size_t)k * PP + p0 + pt * 4;
            if (full) {
                *reinterpret_cast<float4*>(&g_sm2T[base]) = make_float4(a0, a1, a2, a3);
            } else {
                float av[4] = {a0, a1, a2, a3};
#pragma unroll
                for (int r0 = 0; r0 < 4; ++r0) {
                    int p = p0 + pt * 4 + r0;
                    if (p < PP) g_sm2T[(size_t)k * PP + p] = av[r0];
                }
            }
        }
    }
}

// ------------------------- K3: monolithic in-SMEM counting sort + dot ------------------
// One CTA per segment. Source is read 3x from L2 (coalesced, resident); no A buffer.
// Pass 2 saves each element's intra-bin arrival rank (u16) -> pass 3 is atomic-free.
// hist[] keeps exclusive starts after the scan (never mutated), giving exact run
// bounds for the per-bin insertion cleanup.
__global__ void __launch_bounds__(1024)
k3_countsort(const float* __restrict__ WdOut, float* __restrict__ out) {
    extern __shared__ __align__(16) char smem_raw[];
    float* B = (float*)smem_raw;                                 // PP floats
    unsigned int* hist = (unsigned int*)(smem_raw + PP * 4);     // NBINS u32
    unsigned short* rankA =
        (unsigned short*)(smem_raw + PP * 4 + NBINS * 4);        // PP u16
    float* wmin = (float*)(rankA + PP);                          // 32
    float* wmax = wmin + 32;                                     // 32
    unsigned int* wsum = (unsigned int*)(wmax + 32);             // 32

    const int k = blockIdx.x;
    const int t = threadIdx.x;
    const int lane = t & 31, wid = t >> 5;
    const size_t gbase = (size_t)k * PP;
    const float* __restrict__ src = g_sm2T + gbase;

    // ---- pass 1: min/max + zero hist ----
    float mn = __int_as_float(0x7f800000), mx = -mn;
    for (int i = t; i < PP; i += 1024) {
        float x = src[i];
        mn = fminf(mn, x);
        mx = fmaxf(mx, x);
    }
#pragma unroll
    for (int o = 16; o > 0; o >>= 1) {
        mn = fminf(mn, __shfl_xor_sync(0xffffffffu, mn, o));
        mx = fmaxf(mx, __shfl_xor_sync(0xffffffffu, mx, o));
    }
    if (lane == 0) { wmin[wid] = mn; wmax[wid] = mx; }
    for (int b = t; b < NBINS; b += 1024) hist[b] = 0u;
    __syncthreads();
    if (t < 32) {
        float a = wmin[t], b = wmax[t];
#pragma unroll
        for (int o = 16; o > 0; o >>= 1) {
            a = fminf(a, __shfl_xor_sync(0xffffffffu, a, o));
            b = fmaxf(b, __shfl_xor_sync(0xffffffffu, b, o));
        }
        if (t == 0) { wmin[0] = a; wmax[0] = b; }
    }
    __syncthreads();
    mn = wmin[0]; mx = wmax[0];
    const float width = mx - mn;
    const float scale = (width > 0.0f) ? (float)NBINS / width : 0.0f;
    __syncthreads();

    // ---- pass 2: histogram + save intra-bin arrival rank ----
    for (int i = t; i < PP; i += 1024) {
        int bin = min(NBINS - 1, (int)((src[i] - mn) * scale));
        unsigned int old = atomicAdd(&hist[bin], 1u);
        rankA[i] = (unsigned short)old;
    }
    __syncthreads();

    // ---- exclusive scan of hist (16 bins/thread); hist becomes starts ----
    const int bb = t * (NBINS / 1024);
    unsigned int s = 0;
#pragma unroll
    for (int i = 0; i < NBINS / 1024; ++i) s += hist[bb + i];
    unsigned int sc = s;
#pragma unroll
    for (int o = 1; o < 32; o <<= 1) {
        unsigned int u = __shfl_up_sync(0xffffffffu, sc, o);
        if (lane >= o) sc += u;
    }
    if (lane == 31) wsum[wid] = sc;
    __syncthreads();
    if (t < 32) {
        unsigned int v = wsum[t], vs = v;
#pragma unroll
        for (int o = 1; o < 32; o <<= 1) {
            unsigned int u = __shfl_up_sync(0xffffffffu, vs, o);
            if (t >= o) vs += u;
        }
        wsum[t] = vs - v;
    }
    __syncthreads();
    unsigned int run = wsum[wid] + (sc - s);
#pragma unroll
    for (int i = 0; i < NBINS / 1024; ++i) {
        unsigned int c = hist[bb + i];
        hist[bb + i] = run;          // exclusive start; NOT mutated afterwards
        run += c;
    }
    __syncthreads();

    // ---- pass 3: atomic-free scatter ----
    for (int i = t; i < PP; i += 1024) {
        float x = src[i];
        int bin = min(NBINS - 1, (int)((x - mn) * scale));
        B[hist[bin] + rankA[i]] = x;
    }
    __syncthreads();

    // ---- per-bin insertion sort (exact; run b = [hist[b], next start)) ----
    if (scale != 0.0f) {
        for (int b = t; b < NBINS; b += 1024) {
            int st = (int)hist[b];
            int e = (b == NBINS - 1) ? PP : (int)hist[b + 1];
            for (int a2 = st + 1; a2 < e; ++a2) {
                float x = B[a2];
                int j = a2 - 1;
                while (j >= st && B[j] > x) { B[j + 1] = B[j]; --j; }
                B[j + 1] = x;
            }
        }
    }
    __syncthreads();

    // ---- rank-aligned weighted dot ----
    float acc = 0.0f;
    for (int i = t; i < PP; i += 1024)
        acc = fmaf(WdOut[gbase + i], B[i], acc);
#pragma unroll
    for (int o = 16; o > 0; o >>= 1)
        acc += __shfl_down_sync(0xffffffffu, acc, o);
    if (lane == 0) wmin[wid] = acc;
    __syncthreads();
    if (t < 32) {
        float x = wmin[t];
#pragma unroll
        for (int o = 16; o > 0; o >>= 1)
            x += __shfl_down_sync(0xffffffffu, x, o);
        if (t == 0) out[k] = x;
    }
}

// ------------------------- launch -------------------------
extern "C" void kernel_launch(void* const* d_in, const int* in_sizes, int n_in,
                              void* d_out, int out_size) {
    const float* matrix = (const float*)d_in[0];
    const float* WsIn   = (const float*)d_in[1];
    const float* WdIn   = (const float*)d_in[2];
    const float* WsOut  = (const float*)d_in[3];
    const float* WdOut  = (const float*)d_in[4];
    float* out = (float*)d_out;

    cudaFuncSetAttribute(k3_countsort, cudaFuncAttributeMaxDynamicSharedMemorySize,
                         K3_SMEM);

    k0_transpose<<<DE, 192>>>(WsOut);
    k0b_transpose<<<RESTN, 192>>>(WdIn);
    k1_vec<<<PP, 192>>>(matrix, WsIn);
    k2_gemm<<<(PP + TP - 1) / TP, 256>>>();
    k3_countsort<<<KK, 1024, K3_SMEM>>>(WdOut, out);
}